// round 1
// baseline (speedup 1.0000x reference)
#include <cuda_runtime.h>

// Problem constants
#define Nb 8
#define C  64
#define H  256
#define W  256
#define HW (H * W)          // 65536
#define NPIX (Nb * HW)      // 524288

// 128 MiB intermediate ("first" pass result), static device scratch (no alloc).
__device__ float g_inter[(size_t)Nb * C * HW];

__global__ __launch_bounds__(256) void grid_sample_kernel(
    const float* __restrict__ feat,    // [N,C,H,W]
    const float2* __restrict__ grid,   // [N,H,W] of (x,y)
    float* __restrict__ out)           // [N,C,H,W]
{
    int pix = blockIdx.x * blockDim.x + threadIdx.x;
    if (pix >= NPIX) return;

    int n  = pix >> 16;        // / HW
    int hw = pix & (HW - 1);   // % HW

    float2 g = __ldg(&grid[pix]);
    // align_corners=False: ix = ((gx+1)*W - 1) * 0.5
    float ix = ((g.x + 1.0f) * (float)W - 1.0f) * 0.5f;
    float iy = ((g.y + 1.0f) * (float)H - 1.0f) * 0.5f;

    float ix0f = floorf(ix);
    float iy0f = floorf(iy);
    float fx = ix - ix0f;
    float fy = iy - iy0f;

    int x0 = (int)ix0f;
    int y0 = (int)iy0f;
    int x1 = x0 + 1;
    int y1 = y0 + 1;

    float vx0 = (x0 >= 0 && x0 < W) ? 1.0f : 0.0f;
    float vx1 = (x1 >= 0 && x1 < W) ? 1.0f : 0.0f;
    float vy0 = (y0 >= 0 && y0 < H) ? 1.0f : 0.0f;
    float vy1 = (y1 >= 0 && y1 < H) ? 1.0f : 0.0f;

    int cx0 = min(max(x0, 0), W - 1);
    int cx1 = min(max(x1, 0), W - 1);
    int cy0 = min(max(y0, 0), H - 1);
    int cy1 = min(max(y1, 0), H - 1);

    float wx0 = 1.0f - fx, wx1 = fx;
    float wy0 = 1.0f - fy, wy1 = fy;

    // fold validity masks into the bilinear weights -> branch-free inner loop
    float w00 = wx0 * wy0 * vx0 * vy0;
    float w01 = wx1 * wy0 * vx1 * vy0;
    float w10 = wx0 * wy1 * vx0 * vy1;
    float w11 = wx1 * wy1 * vx1 * vy1;

    int o00 = cy0 * W + cx0;
    int o01 = cy0 * W + cx1;
    int o10 = cy1 * W + cx0;
    int o11 = cy1 * W + cx1;

    const float* fb = feat + (size_t)n * C * HW;
    float*       ob = out  + (size_t)n * C * HW + hw;

    #pragma unroll 8
    for (int c = 0; c < C; ++c) {
        const float* f = fb + (size_t)c * HW;
        float v = __ldg(f + o00) * w00
                + __ldg(f + o01) * w01
                + __ldg(f + o10) * w10
                + __ldg(f + o11) * w11;
        ob[(size_t)c * HW] = v;
    }
}

extern "C" void kernel_launch(void* const* d_in, const int* in_sizes, int n_in,
                              void* d_out, int out_size)
{
    const float*  feat = (const float*)d_in[0];
    const float2* grid = (const float2*)d_in[1];
    float* out = (float*)d_out;

    float* inter = nullptr;
    cudaGetSymbolAddress((void**)&inter, g_inter);

    dim3 block(256);
    dim3 gridDim((NPIX + 255) / 256);

    // pass 1: sample feature -> inter
    grid_sample_kernel<<<gridDim, block>>>(feat, grid, inter);
    // pass 2: sample inter -> out
    grid_sample_kernel<<<gridDim, block>>>(inter, grid, out);
}

// round 3
// speedup vs baseline: 3.8901x; 3.8901x over previous
#include <cuda_runtime.h>

#define Nb 8
#define C  64
#define H  256
#define W  256
#define HW (H * W)            // 65536
#define NPIX (Nb * HW)        // 524288
#define PLANE ((size_t)C * HW) // floats per batch

// Two 128 MiB NHWC scratch buffers (static device memory, no alloc).
__device__ float g_a[(size_t)Nb * PLANE];
__device__ float g_b[(size_t)Nb * PLANE];

// Generic batched 32x32 tiled transpose: in is rows x cols row-major per batch,
// out is cols x rows. blockDim = (32, 8). grid = (cols/32, rows/32, Nb).
__global__ __launch_bounds__(256) void transpose_kernel(
    const float* __restrict__ in, float* __restrict__ out, int rows, int cols)
{
    __shared__ float tile[32][33];
    size_t boff = (size_t)blockIdx.z * rows * cols;
    int c0 = blockIdx.x * 32;
    int r0 = blockIdx.y * 32;

    #pragma unroll
    for (int j = 0; j < 4; ++j) {
        int r = r0 + threadIdx.y + j * 8;
        tile[threadIdx.y + j * 8][threadIdx.x] =
            in[boff + (size_t)r * cols + c0 + threadIdx.x];
    }
    __syncthreads();
    #pragma unroll
    for (int j = 0; j < 4; ++j) {
        int cc = c0 + threadIdx.y + j * 8;
        out[boff + (size_t)cc * rows + r0 + threadIdx.x] =
            tile[threadIdx.x][threadIdx.y + j * 8];
    }
}

// Bilinear grid sample with NHWC feature and NHWC output.
// 16 threads per output pixel; each thread handles 4 channels (float4).
__global__ __launch_bounds__(256) void gather_nhwc_kernel(
    const float* __restrict__ feat,    // [N,H,W,C]
    const float2* __restrict__ grid,   // [N,H,W]
    float* __restrict__ out)           // [N,H,W,C]
{
    int tid = blockIdx.x * blockDim.x + threadIdx.x;
    int pix = tid >> 4;           // pixel index
    int c4  = (tid & 15) << 2;    // channel offset (0,4,...,60)
    if (pix >= NPIX) return;

    int n  = pix >> 16;
    // hw = pix & 65535 implicit in pix-based addressing below

    float2 g = __ldg(&grid[pix]);
    float ix = ((g.x + 1.0f) * (float)W - 1.0f) * 0.5f;
    float iy = ((g.y + 1.0f) * (float)H - 1.0f) * 0.5f;

    float ix0f = floorf(ix);
    float iy0f = floorf(iy);
    float fx = ix - ix0f;
    float fy = iy - iy0f;

    int x0 = (int)ix0f, y0 = (int)iy0f;
    int x1 = x0 + 1,    y1 = y0 + 1;

    float vx0 = (x0 >= 0 && x0 < W) ? 1.0f : 0.0f;
    float vx1 = (x1 >= 0 && x1 < W) ? 1.0f : 0.0f;
    float vy0 = (y0 >= 0 && y0 < H) ? 1.0f : 0.0f;
    float vy1 = (y1 >= 0 && y1 < H) ? 1.0f : 0.0f;

    int cx0 = min(max(x0, 0), W - 1);
    int cx1 = min(max(x1, 0), W - 1);
    int cy0 = min(max(y0, 0), H - 1);
    int cy1 = min(max(y1, 0), H - 1);

    float w00 = (1.0f - fx) * (1.0f - fy) * vx0 * vy0;
    float w01 = fx * (1.0f - fy) * vx1 * vy0;
    float w10 = (1.0f - fx) * fy * vx0 * vy1;
    float w11 = fx * fy * vx1 * vy1;

    const float* fb = feat + (size_t)n * PLANE;
    const float4 a = __ldg((const float4*)(fb + ((size_t)(cy0 * W + cx0) << 6) + c4));
    const float4 b = __ldg((const float4*)(fb + ((size_t)(cy0 * W + cx1) << 6) + c4));
    const float4 c = __ldg((const float4*)(fb + ((size_t)(cy1 * W + cx0) << 6) + c4));
    const float4 d = __ldg((const float4*)(fb + ((size_t)(cy1 * W + cx1) << 6) + c4));

    float4 r;
    r.x = a.x * w00 + b.x * w01 + c.x * w10 + d.x * w11;
    r.y = a.y * w00 + b.y * w01 + c.y * w10 + d.y * w11;
    r.z = a.z * w00 + b.z * w01 + c.z * w10 + d.z * w11;
    r.w = a.w * w00 + b.w * w01 + c.w * w10 + d.w * w11;

    *((float4*)(out + ((size_t)pix << 6) + c4)) = r;
}

extern "C" void kernel_launch(void* const* d_in, const int* in_sizes, int n_in,
                              void* d_out, int out_size)
{
    const float*  feat = (const float*)d_in[0];
    const float2* grid = (const float2*)d_in[1];
    float* out = (float*)d_out;

    float *a = nullptr, *b = nullptr;
    cudaGetSymbolAddress((void**)&a, g_a);
    cudaGetSymbolAddress((void**)&b, g_b);

    dim3 tb(32, 8);

    // 1. feature NCHW -> NHWC   (rows=C, cols=HW)
    transpose_kernel<<<dim3(HW / 32, C / 32, Nb), tb>>>(feat, a, C, HW);

    // 2. pass 1 gather (NHWC -> NHWC)
    int gblocks = (NPIX * 16) / 256;
    gather_nhwc_kernel<<<gblocks, 256>>>(a, grid, b);

    // 3. pass 2 gather (NHWC -> NHWC), reuse g_a
    gather_nhwc_kernel<<<gblocks, 256>>>(b, grid, a);

    // 4. result NHWC -> NCHW   (rows=HW, cols=C)
    transpose_kernel<<<dim3(C / 32, HW / 32, Nb), tb>>>(a, out, HW, C);
}

// round 4
// speedup vs baseline: 4.0969x; 1.0531x over previous
#include <cuda_runtime.h>

#define Nb 8
#define C  64
#define H  256
#define W  256
#define HW (H * W)             // 65536
#define NPIX (Nb * HW)         // 524288
#define PLANE ((size_t)C * HW) // floats per batch

// Two 128 MiB NHWC scratch buffers (static device memory, no alloc).
__device__ float g_a[(size_t)Nb * PLANE];
__device__ float g_b[(size_t)Nb * PLANE];

// ---------------------------------------------------------------------------
// Batched 32x32 tiled transpose (NCHW -> NHWC). blockDim=(32,8).
// ---------------------------------------------------------------------------
__global__ __launch_bounds__(256) void transpose_kernel(
    const float* __restrict__ in, float* __restrict__ out, int rows, int cols)
{
    __shared__ float tile[32][33];
    size_t boff = (size_t)blockIdx.z * rows * cols;
    int c0 = blockIdx.x * 32;
    int r0 = blockIdx.y * 32;

    #pragma unroll
    for (int j = 0; j < 4; ++j) {
        int r = r0 + threadIdx.y + j * 8;
        tile[threadIdx.y + j * 8][threadIdx.x] =
            in[boff + (size_t)r * cols + c0 + threadIdx.x];
    }
    __syncthreads();
    #pragma unroll
    for (int j = 0; j < 4; ++j) {
        int cc = c0 + threadIdx.y + j * 8;
        out[boff + (size_t)cc * rows + r0 + threadIdx.x] =
            tile[threadIdx.x][threadIdx.y + j * 8];
    }
}

// ---------------------------------------------------------------------------
// Shared coordinate/weight computation
// ---------------------------------------------------------------------------
struct SampleW {
    float w00, w01, w10, w11;
    int o00, o01, o10, o11;   // pixel offsets (y*W+x) into the feature plane
};

__device__ __forceinline__ SampleW compute_weights(float2 g)
{
    float ix = ((g.x + 1.0f) * (float)W - 1.0f) * 0.5f;
    float iy = ((g.y + 1.0f) * (float)H - 1.0f) * 0.5f;

    float ix0f = floorf(ix);
    float iy0f = floorf(iy);
    float fx = ix - ix0f;
    float fy = iy - iy0f;

    int x0 = (int)ix0f, y0 = (int)iy0f;
    int x1 = x0 + 1,    y1 = y0 + 1;

    float vx0 = (x0 >= 0 && x0 < W) ? 1.0f : 0.0f;
    float vx1 = (x1 >= 0 && x1 < W) ? 1.0f : 0.0f;
    float vy0 = (y0 >= 0 && y0 < H) ? 1.0f : 0.0f;
    float vy1 = (y1 >= 0 && y1 < H) ? 1.0f : 0.0f;

    int cx0 = min(max(x0, 0), W - 1);
    int cx1 = min(max(x1, 0), W - 1);
    int cy0 = min(max(y0, 0), H - 1);
    int cy1 = min(max(y1, 0), H - 1);

    SampleW s;
    s.w00 = (1.0f - fx) * (1.0f - fy) * vx0 * vy0;
    s.w01 = fx * (1.0f - fy) * vx1 * vy0;
    s.w10 = (1.0f - fx) * fy * vx0 * vy1;
    s.w11 = fx * fy * vx1 * vy1;
    s.o00 = cy0 * W + cx0;
    s.o01 = cy0 * W + cx1;
    s.o10 = cy1 * W + cx0;
    s.o11 = cy1 * W + cx1;
    return s;
}

// ---------------------------------------------------------------------------
// Pass 1: NHWC feature -> NHWC out. 16 threads/pixel, each does 4 channels.
// ---------------------------------------------------------------------------
__global__ __launch_bounds__(256) void gather_nhwc_kernel(
    const float* __restrict__ feat,    // [N,H,W,C]
    const float2* __restrict__ grid,   // [N,H,W]
    float* __restrict__ out)           // [N,H,W,C]
{
    int tid = blockIdx.x * blockDim.x + threadIdx.x;
    int pix = tid >> 4;
    int c4  = (tid & 15) << 2;
    if (pix >= NPIX) return;

    int n = pix >> 16;
    SampleW s = compute_weights(__ldg(&grid[pix]));

    const float* fb = feat + (size_t)n * PLANE;
    const float4 a = __ldg((const float4*)(fb + ((size_t)s.o00 << 6) + c4));
    const float4 b = __ldg((const float4*)(fb + ((size_t)s.o01 << 6) + c4));
    const float4 c = __ldg((const float4*)(fb + ((size_t)s.o10 << 6) + c4));
    const float4 d = __ldg((const float4*)(fb + ((size_t)s.o11 << 6) + c4));

    float4 r;
    r.x = a.x * s.w00 + b.x * s.w01 + c.x * s.w10 + d.x * s.w11;
    r.y = a.y * s.w00 + b.y * s.w01 + c.y * s.w10 + d.y * s.w11;
    r.z = a.z * s.w00 + b.z * s.w01 + c.z * s.w10 + d.z * s.w11;
    r.w = a.w * s.w00 + b.w * s.w01 + c.w * s.w10 + d.w * s.w11;

    *((float4*)(out + ((size_t)pix << 6) + c4)) = r;
}

// ---------------------------------------------------------------------------
// Pass 2 (fused): NHWC feature -> NCHW out directly, via smem staging.
// Block = 256 threads = 64 consecutive pixels x 4 channel-quarters.
// ---------------------------------------------------------------------------
__global__ __launch_bounds__(256) void gather_nhwc_to_nchw_kernel(
    const float* __restrict__ feat,    // [N,H,W,C] intermediate
    const float2* __restrict__ grid,   // [N,H,W]
    float* __restrict__ out)           // [N,C,H,W]
{
    __shared__ float st[64][65];       // [local pixel][channel], pad -> no LDS conflicts

    int pix0 = blockIdx.x * 64;        // 64 consecutive pixels, same n (HW % 64 == 0)
    int n   = pix0 >> 16;
    int hw0 = pix0 & (HW - 1);

    int t   = threadIdx.x;
    int p   = t >> 2;                  // local pixel 0..63
    int sub = t & 3;                   // channel quarter

    SampleW s = compute_weights(__ldg(&grid[pix0 + p]));

    const float* fb = feat + (size_t)n * PLANE;
    const float* p00 = fb + ((size_t)s.o00 << 6);
    const float* p01 = fb + ((size_t)s.o01 << 6);
    const float* p10 = fb + ((size_t)s.o10 << 6);
    const float* p11 = fb + ((size_t)s.o11 << 6);

    #pragma unroll
    for (int q = 0; q < 4; ++q) {
        int c = (sub << 4) + (q << 2); // this thread's channels: sub*16 + q*4
        float4 a = __ldg((const float4*)(p00 + c));
        float4 b = __ldg((const float4*)(p01 + c));
        float4 cc = __ldg((const float4*)(p10 + c));
        float4 d = __ldg((const float4*)(p11 + c));

        st[p][c + 0] = a.x * s.w00 + b.x * s.w01 + cc.x * s.w10 + d.x * s.w11;
        st[p][c + 1] = a.y * s.w00 + b.y * s.w01 + cc.y * s.w10 + d.y * s.w11;
        st[p][c + 2] = a.z * s.w00 + b.z * s.w01 + cc.z * s.w10 + d.z * s.w11;
        st[p][c + 3] = a.w * s.w00 + b.w * s.w01 + cc.w * s.w10 + d.w * s.w11;
    }
    __syncthreads();

    // Write phase: NCHW. Each warp: 32 consecutive px, fixed channel -> 128B stores.
    int px = t & 63;                   // local pixel
    int cg = t >> 6;                   // channel group 0..3
    float* ob = out + (size_t)n * PLANE + hw0 + px;
    #pragma unroll
    for (int c = 0; c < 16; ++c) {
        int ch = cg * 16 + c;
        ob[(size_t)ch * HW] = st[px][ch];
    }
}

extern "C" void kernel_launch(void* const* d_in, const int* in_sizes, int n_in,
                              void* d_out, int out_size)
{
    const float*  feat = (const float*)d_in[0];
    const float2* grid = (const float2*)d_in[1];
    float* out = (float*)d_out;

    float *a = nullptr, *b = nullptr;
    cudaGetSymbolAddress((void**)&a, g_a);
    cudaGetSymbolAddress((void**)&b, g_b);

    // 1. feature NCHW -> NHWC
    transpose_kernel<<<dim3(HW / 32, C / 32, Nb), dim3(32, 8)>>>(feat, a, C, HW);

    // 2. pass 1 gather (NHWC -> NHWC)
    gather_nhwc_kernel<<<(NPIX * 16) / 256, 256>>>(a, grid, b);

    // 3. pass 2 gather fused with output transpose (NHWC -> NCHW)
    gather_nhwc_to_nchw_kernel<<<NPIX / 64, 256>>>(b, grid, out);
}

// round 5
// speedup vs baseline: 4.3492x; 1.0616x over previous
#include <cuda_runtime.h>

#define Nb 8
#define C  64
#define H  256
#define W  256
#define HW (H * W)             // 65536
#define NPIX (Nb * HW)         // 524288
#define PLANE ((size_t)C * HW) // floats per batch

// Two 128 MiB NHWC scratch buffers (static device memory, no alloc).
__device__ float g_a[(size_t)Nb * PLANE];
__device__ float g_b[(size_t)Nb * PLANE];

// ---------------------------------------------------------------------------
// NCHW -> NHWC transpose. Block = (32,8) = 256 threads, handles a full
// 64(ch) x 32(hw) tile: 8 independent loads per thread (MLP=8), one sync,
// 8 coalesced stores. grid = (HW/32, 1, Nb).
// ---------------------------------------------------------------------------
__global__ __launch_bounds__(256) void nchw_to_nhwc_kernel(
    const float* __restrict__ in, float* __restrict__ out)
{
    __shared__ float tile[64][33];     // [channel][hw_local]
    size_t boff = (size_t)blockIdx.z * PLANE;
    int hw0 = blockIdx.x * 32;
    int tx = threadIdx.x, ty = threadIdx.y;

    // load: 8 rows (channels) per thread, coalesced along hw
    #pragma unroll
    for (int j = 0; j < 8; ++j) {
        int ch = ty + j * 8;
        tile[ch][tx] = in[boff + (size_t)ch * HW + hw0 + tx];
    }
    __syncthreads();

    // store: lanes span channels (contiguous in NHWC), conflict-free LDS
    #pragma unroll
    for (int j = 0; j < 8; ++j) {
        int hwl = ty + (j >> 1) * 8;
        int ch  = tx + (j & 1) * 32;
        out[boff + (size_t)(hw0 + hwl) * 64 + ch] = tile[ch][hwl];
    }
}

// ---------------------------------------------------------------------------
// Shared coordinate/weight computation
// ---------------------------------------------------------------------------
struct SampleW {
    float w00, w01, w10, w11;
    int o00, o01, o10, o11;
};

__device__ __forceinline__ SampleW compute_weights(float2 g)
{
    float ix = ((g.x + 1.0f) * (float)W - 1.0f) * 0.5f;
    float iy = ((g.y + 1.0f) * (float)H - 1.0f) * 0.5f;

    float ix0f = floorf(ix);
    float iy0f = floorf(iy);
    float fx = ix - ix0f;
    float fy = iy - iy0f;

    int x0 = (int)ix0f, y0 = (int)iy0f;
    int x1 = x0 + 1,    y1 = y0 + 1;

    float vx0 = (x0 >= 0 && x0 < W) ? 1.0f : 0.0f;
    float vx1 = (x1 >= 0 && x1 < W) ? 1.0f : 0.0f;
    float vy0 = (y0 >= 0 && y0 < H) ? 1.0f : 0.0f;
    float vy1 = (y1 >= 0 && y1 < H) ? 1.0f : 0.0f;

    int cx0 = min(max(x0, 0), W - 1);
    int cx1 = min(max(x1, 0), W - 1);
    int cy0 = min(max(y0, 0), H - 1);
    int cy1 = min(max(y1, 0), H - 1);

    SampleW s;
    s.w00 = (1.0f - fx) * (1.0f - fy) * vx0 * vy0;
    s.w01 = fx * (1.0f - fy) * vx1 * vy0;
    s.w10 = (1.0f - fx) * fy * vx0 * vy1;
    s.w11 = fx * fy * vx1 * vy1;
    s.o00 = cy0 * W + cx0;
    s.o01 = cy0 * W + cx1;
    s.o10 = cy1 * W + cx0;
    s.o11 = cy1 * W + cx1;
    return s;
}

// ---------------------------------------------------------------------------
// Pass 1: NHWC feature -> NHWC out. 16 threads/pixel, each does 4 channels.
// ---------------------------------------------------------------------------
__global__ __launch_bounds__(256) void gather_nhwc_kernel(
    const float* __restrict__ feat,
    const float2* __restrict__ grid,
    float* __restrict__ out)
{
    int tid = blockIdx.x * blockDim.x + threadIdx.x;
    int pix = tid >> 4;
    int c4  = (tid & 15) << 2;
    if (pix >= NPIX) return;

    int n = pix >> 16;
    SampleW s = compute_weights(__ldg(&grid[pix]));

    const float* fb = feat + (size_t)n * PLANE;
    const float4 a = __ldg((const float4*)(fb + ((size_t)s.o00 << 6) + c4));
    const float4 b = __ldg((const float4*)(fb + ((size_t)s.o01 << 6) + c4));
    const float4 c = __ldg((const float4*)(fb + ((size_t)s.o10 << 6) + c4));
    const float4 d = __ldg((const float4*)(fb + ((size_t)s.o11 << 6) + c4));

    float4 r;
    r.x = a.x * s.w00 + b.x * s.w01 + c.x * s.w10 + d.x * s.w11;
    r.y = a.y * s.w00 + b.y * s.w01 + c.y * s.w10 + d.y * s.w11;
    r.z = a.z * s.w00 + b.z * s.w01 + c.z * s.w10 + d.z * s.w11;
    r.w = a.w * s.w00 + b.w * s.w01 + c.w * s.w10 + d.w * s.w11;

    *((float4*)(out + ((size_t)pix << 6) + c4)) = r;
}

// ---------------------------------------------------------------------------
// Pass 2 (fused): NHWC feature -> NCHW out, via smem staging.
// Block = 256 threads = 64 consecutive pixels x 4 channel-quarters.
// Write phase uses STG.128 (4 consecutive hw per lane).
// ---------------------------------------------------------------------------
__global__ __launch_bounds__(256) void gather_nhwc_to_nchw_kernel(
    const float* __restrict__ feat,    // [N,H,W,C] intermediate
    const float2* __restrict__ grid,   // [N,H,W]
    float* __restrict__ out)           // [N,C,H,W]
{
    __shared__ float st[64][65];       // [local pixel][channel]

    int pix0 = blockIdx.x * 64;
    int n   = pix0 >> 16;
    int hw0 = pix0 & (HW - 1);

    int t   = threadIdx.x;
    int p   = t >> 2;                  // local pixel 0..63
    int sub = t & 3;                   // channel quarter

    SampleW s = compute_weights(__ldg(&grid[pix0 + p]));

    const float* fb = feat + (size_t)n * PLANE;
    const float* p00 = fb + ((size_t)s.o00 << 6);
    const float* p01 = fb + ((size_t)s.o01 << 6);
    const float* p10 = fb + ((size_t)s.o10 << 6);
    const float* p11 = fb + ((size_t)s.o11 << 6);

    #pragma unroll
    for (int q = 0; q < 4; ++q) {
        int c = (sub << 4) + (q << 2);
        float4 a = __ldg((const float4*)(p00 + c));
        float4 b = __ldg((const float4*)(p01 + c));
        float4 cc = __ldg((const float4*)(p10 + c));
        float4 d = __ldg((const float4*)(p11 + c));

        st[p][c + 0] = a.x * s.w00 + b.x * s.w01 + cc.x * s.w10 + d.x * s.w11;
        st[p][c + 1] = a.y * s.w00 + b.y * s.w01 + cc.y * s.w10 + d.y * s.w11;
        st[p][c + 2] = a.z * s.w00 + b.z * s.w01 + cc.z * s.w10 + d.z * s.w11;
        st[p][c + 3] = a.w * s.w00 + b.w * s.w01 + cc.w * s.w10 + d.w * s.w11;
    }
    __syncthreads();

    // Write phase: each lane stores float4 = 4 consecutive hw, fixed channel.
    // Half-warp (16 lanes) covers 64 hw = 256B contiguous per channel.
    int px4 = (t & 15) << 2;           // local pixel base 0,4,...,60
    int ch0 = t >> 4;                  // channel 0..15
    float* ob = out + (size_t)n * PLANE + hw0 + px4;
    #pragma unroll
    for (int i = 0; i < 4; ++i) {
        int ch = ch0 + (i << 4);
        float4 v;
        v.x = st[px4 + 0][ch];
        v.y = st[px4 + 1][ch];
        v.z = st[px4 + 2][ch];
        v.w = st[px4 + 3][ch];
        *((float4*)(ob + (size_t)ch * HW)) = v;
    }
}

extern "C" void kernel_launch(void* const* d_in, const int* in_sizes, int n_in,
                              void* d_out, int out_size)
{
    const float*  feat = (const float*)d_in[0];
    const float2* grid = (const float2*)d_in[1];
    float* out = (float*)d_out;

    float *a = nullptr, *b = nullptr;
    cudaGetSymbolAddress((void**)&a, g_a);
    cudaGetSymbolAddress((void**)&b, g_b);

    // 1. feature NCHW -> NHWC
    nchw_to_nhwc_kernel<<<dim3(HW / 32, 1, Nb), dim3(32, 8)>>>(feat, a);

    // 2. pass 1 gather (NHWC -> NHWC)
    gather_nhwc_kernel<<<(NPIX * 16) / 256, 256>>>(a, grid, b);

    // 3. pass 2 gather fused with output transpose (NHWC -> NCHW)
    gather_nhwc_to_nchw_kernel<<<NPIX / 64, 256>>>(b, grid, out);
}

// round 6
// speedup vs baseline: 4.4170x; 1.0156x over previous
#include <cuda_runtime.h>

#define Nb 8
#define C  64
#define H  256
#define W  256
#define HW (H * W)             // 65536
#define NPIX (Nb * HW)         // 524288
#define PLANE ((size_t)C * HW) // floats per batch

// Two 128 MiB NHWC scratch buffers (static device memory, no alloc).
__device__ float g_a[(size_t)Nb * PLANE];
__device__ float g_b[(size_t)Nb * PLANE];

// ---------------------------------------------------------------------------
// NCHW -> NHWC transpose. Block=(32,8), 64ch x 32hw tile. (unchanged, 39us)
// ---------------------------------------------------------------------------
__global__ __launch_bounds__(256) void nchw_to_nhwc_kernel(
    const float* __restrict__ in, float* __restrict__ out)
{
    __shared__ float tile[64][33];
    size_t boff = (size_t)blockIdx.z * PLANE;
    int hw0 = blockIdx.x * 32;
    int tx = threadIdx.x, ty = threadIdx.y;

    #pragma unroll
    for (int j = 0; j < 8; ++j) {
        int ch = ty + j * 8;
        tile[ch][tx] = in[boff + (size_t)ch * HW + hw0 + tx];
    }
    __syncthreads();

    #pragma unroll
    for (int j = 0; j < 8; ++j) {
        int hwl = ty + (j >> 1) * 8;
        int ch  = tx + (j & 1) * 32;
        out[boff + (size_t)(hw0 + hwl) * 64 + ch] = tile[ch][hwl];
    }
}

// ---------------------------------------------------------------------------
// Shared coordinate/weight computation
// ---------------------------------------------------------------------------
struct SampleW {
    float w00, w01, w10, w11;
    int o00, o01, o10, o11;
};

__device__ __forceinline__ SampleW compute_weights(float2 g)
{
    float ix = ((g.x + 1.0f) * (float)W - 1.0f) * 0.5f;
    float iy = ((g.y + 1.0f) * (float)H - 1.0f) * 0.5f;

    float ix0f = floorf(ix);
    float iy0f = floorf(iy);
    float fx = ix - ix0f;
    float fy = iy - iy0f;

    int x0 = (int)ix0f, y0 = (int)iy0f;
    int x1 = x0 + 1,    y1 = y0 + 1;

    float vx0 = (x0 >= 0 && x0 < W) ? 1.0f : 0.0f;
    float vx1 = (x1 >= 0 && x1 < W) ? 1.0f : 0.0f;
    float vy0 = (y0 >= 0 && y0 < H) ? 1.0f : 0.0f;
    float vy1 = (y1 >= 0 && y1 < H) ? 1.0f : 0.0f;

    int cx0 = min(max(x0, 0), W - 1);
    int cx1 = min(max(x1, 0), W - 1);
    int cy0 = min(max(y0, 0), H - 1);
    int cy1 = min(max(y1, 0), H - 1);

    SampleW s;
    s.w00 = (1.0f - fx) * (1.0f - fy) * vx0 * vy0;
    s.w01 = fx * (1.0f - fy) * vx1 * vy0;
    s.w10 = (1.0f - fx) * fy * vx0 * vy1;
    s.w11 = fx * fy * vx1 * vy1;
    s.o00 = cy0 * W + cx0;
    s.o01 = cy0 * W + cx1;
    s.o10 = cy1 * W + cx0;
    s.o11 = cy1 * W + cx1;
    return s;
}

__device__ __forceinline__ float4 bilerp4(const float* fb, const SampleW& s, int c4)
{
    const float4 a = __ldg((const float4*)(fb + ((size_t)s.o00 << 6) + c4));
    const float4 b = __ldg((const float4*)(fb + ((size_t)s.o01 << 6) + c4));
    const float4 c = __ldg((const float4*)(fb + ((size_t)s.o10 << 6) + c4));
    const float4 d = __ldg((const float4*)(fb + ((size_t)s.o11 << 6) + c4));
    float4 r;
    r.x = a.x * s.w00 + b.x * s.w01 + c.x * s.w10 + d.x * s.w11;
    r.y = a.y * s.w00 + b.y * s.w01 + c.y * s.w10 + d.y * s.w11;
    r.z = a.z * s.w00 + b.z * s.w01 + c.z * s.w10 + d.z * s.w11;
    r.w = a.w * s.w00 + b.w * s.w01 + c.w * s.w10 + d.w * s.w11;
    return r;
}

// ---------------------------------------------------------------------------
// Pass 1: NHWC -> NHWC. 16 threads/pixel, 4 channels each. (unchanged, 59us)
// ---------------------------------------------------------------------------
__global__ __launch_bounds__(256) void gather_nhwc_kernel(
    const float* __restrict__ feat,
    const float2* __restrict__ grid,
    float* __restrict__ out)
{
    int tid = blockIdx.x * blockDim.x + threadIdx.x;
    int pix = tid >> 4;
    int c4  = (tid & 15) << 2;
    if (pix >= NPIX) return;

    int n = pix >> 16;
    SampleW s = compute_weights(__ldg(&grid[pix]));
    float4 r = bilerp4(feat + (size_t)n * PLANE, s, c4);
    *((float4*)(out + ((size_t)pix << 6) + c4)) = r;
}

// ---------------------------------------------------------------------------
// Pass 2 (fused): NHWC -> NCHW. Block = 512 threads = 32 pixels x 16 chunks.
// Gather phase mirrors pass 1 (4 LDG.128 per thread); epilogue is
// 1 STS.128 + sync + 4 scalar LDS + 1 STG.128 per thread.
// ---------------------------------------------------------------------------
__global__ __launch_bounds__(512) void gather_nhwc_to_nchw_kernel(
    const float* __restrict__ feat,    // [N,H,W,C] intermediate
    const float2* __restrict__ grid,   // [N,H,W]
    float* __restrict__ out)           // [N,C,H,W]
{
    __shared__ float st[32][68];       // [local pixel][channel], stride 68 (16B aligned)

    int pix0 = blockIdx.x * 32;        // 32 consecutive pixels, same batch
    int n   = pix0 >> 16;
    int hw0 = pix0 & (HW - 1);

    int t  = threadIdx.x;
    int p  = t >> 4;                   // local pixel 0..31
    int c4 = (t & 15) << 2;            // channel chunk 0,4,...,60

    SampleW s = compute_weights(__ldg(&grid[pix0 + p]));
    float4 r = bilerp4(feat + (size_t)n * PLANE, s, c4);

    *((float4*)(&st[p][c4])) = r;      // STS.128, conflict-free
    __syncthreads();

    // Write phase: each thread emits one float4 of NCHW (4 consecutive hw).
    int ch  = t & 63;                  // channel 0..63 (ch mod 32 distinct per warp)
    int px4 = (t >> 6) << 2;           // local pixel base 0,4,...,28

    float4 v;
    v.x = st[px4 + 0][ch];
    v.y = st[px4 + 1][ch];
    v.z = st[px4 + 2][ch];
    v.w = st[px4 + 3][ch];
    *((float4*)(out + (size_t)n * PLANE + (size_t)ch * HW + hw0 + px4)) = v;
}

extern "C" void kernel_launch(void* const* d_in, const int* in_sizes, int n_in,
                              void* d_out, int out_size)
{
    const float*  feat = (const float*)d_in[0];
    const float2* grid = (const float2*)d_in[1];
    float* out = (float*)d_out;

    float *a = nullptr, *b = nullptr;
    cudaGetSymbolAddress((void**)&a, g_a);
    cudaGetSymbolAddress((void**)&b, g_b);

    // 1. feature NCHW -> NHWC
    nchw_to_nhwc_kernel<<<dim3(HW / 32, 1, Nb), dim3(32, 8)>>>(feat, a);

    // 2. pass 1 gather (NHWC -> NHWC)
    gather_nhwc_kernel<<<(NPIX * 16) / 256, 256>>>(a, grid, b);

    // 3. pass 2 gather fused with output transpose (NHWC -> NCHW)
    gather_nhwc_to_nchw_kernel<<<NPIX / 32, 512>>>(b, grid, out);
}

// round 8
// speedup vs baseline: 5.2126x; 1.1801x over previous
#include <cuda_runtime.h>

#define Nb 8
#define C  64
#define H  256
#define W  256
#define HW (H * W)             // 65536
#define NPIX (Nb * HW)         // 524288
#define PLANE ((size_t)C * HW) // floats per batch

// Two 128 MiB NHWC scratch buffers (static device memory, no alloc).
__device__ float g_a[(size_t)Nb * PLANE];
__device__ float g_b[(size_t)Nb * PLANE];

// ---------------------------------------------------------------------------
// NCHW -> NHWC transpose. Block=(32,8), 64ch x 32hw tile. (unchanged, 39us)
// ---------------------------------------------------------------------------
__global__ __launch_bounds__(256) void nchw_to_nhwc_kernel(
    const float* __restrict__ in, float* __restrict__ out)
{
    __shared__ float tile[64][33];
    size_t boff = (size_t)blockIdx.z * PLANE;
    int hw0 = blockIdx.x * 32;
    int tx = threadIdx.x, ty = threadIdx.y;

    #pragma unroll
    for (int j = 0; j < 8; ++j) {
        int ch = ty + j * 8;
        tile[ch][tx] = in[boff + (size_t)ch * HW + hw0 + tx];
    }
    __syncthreads();

    #pragma unroll
    for (int j = 0; j < 8; ++j) {
        int hwl = ty + (j >> 1) * 8;
        int ch  = tx + (j & 1) * 32;
        out[boff + (size_t)(hw0 + hwl) * 64 + ch] = tile[ch][hwl];
    }
}

// ---------------------------------------------------------------------------
// Shared coordinate/weight computation
// ---------------------------------------------------------------------------
struct SampleW {
    float w00, w01, w10, w11;
    int o00, o01, o10, o11;
};

__device__ __forceinline__ SampleW compute_weights(float2 g)
{
    float ix = ((g.x + 1.0f) * (float)W - 1.0f) * 0.5f;
    float iy = ((g.y + 1.0f) * (float)H - 1.0f) * 0.5f;

    float ix0f = floorf(ix);
    float iy0f = floorf(iy);
    float fx = ix - ix0f;
    float fy = iy - iy0f;

    int x0 = (int)ix0f, y0 = (int)iy0f;
    int x1 = x0 + 1,    y1 = y0 + 1;

    float vx0 = (x0 >= 0 && x0 < W) ? 1.0f : 0.0f;
    float vx1 = (x1 >= 0 && x1 < W) ? 1.0f : 0.0f;
    float vy0 = (y0 >= 0 && y0 < H) ? 1.0f : 0.0f;
    float vy1 = (y1 >= 0 && y1 < H) ? 1.0f : 0.0f;

    int cx0 = min(max(x0, 0), W - 1);
    int cx1 = min(max(x1, 0), W - 1);
    int cy0 = min(max(y0, 0), H - 1);
    int cy1 = min(max(y1, 0), H - 1);

    SampleW s;
    s.w00 = (1.0f - fx) * (1.0f - fy) * vx0 * vy0;
    s.w01 = fx * (1.0f - fy) * vx1 * vy0;
    s.w10 = (1.0f - fx) * fy * vx0 * vy1;
    s.w11 = fx * fy * vx1 * vy1;
    s.o00 = cy0 * W + cx0;
    s.o01 = cy0 * W + cx1;
    s.o10 = cy1 * W + cx0;
    s.o11 = cy1 * W + cx1;
    return s;
}

__device__ __forceinline__ float4 bilerp4(const float* fb, const SampleW& s, int c4)
{
    const float4 a = __ldg((const float4*)(fb + ((size_t)s.o00 << 6) + c4));
    const float4 b = __ldg((const float4*)(fb + ((size_t)s.o01 << 6) + c4));
    const float4 c = __ldg((const float4*)(fb + ((size_t)s.o10 << 6) + c4));
    const float4 d = __ldg((const float4*)(fb + ((size_t)s.o11 << 6) + c4));
    float4 r;
    r.x = a.x * s.w00 + b.x * s.w01 + c.x * s.w10 + d.x * s.w11;
    r.y = a.y * s.w00 + b.y * s.w01 + c.y * s.w10 + d.y * s.w11;
    r.z = a.z * s.w00 + b.z * s.w01 + c.z * s.w10 + d.z * s.w11;
    r.w = a.w * s.w00 + b.w * s.w01 + c.w * s.w10 + d.w * s.w11;
    return r;
}

// ---------------------------------------------------------------------------
// Pass 1: NHWC -> NHWC. 16 threads/pixel, 4 channels each. (unchanged, 59us)
// ---------------------------------------------------------------------------
__global__ __launch_bounds__(256) void gather_nhwc_kernel(
    const float* __restrict__ feat,
    const float2* __restrict__ grid,
    float* __restrict__ out)
{
    int tid = blockIdx.x * blockDim.x + threadIdx.x;
    int pix = tid >> 4;
    int c4  = (tid & 15) << 2;
    if (pix >= NPIX) return;

    int n = pix >> 16;
    SampleW s = compute_weights(__ldg(&grid[pix]));
    float4 r = bilerp4(feat + (size_t)n * PLANE, s, c4);
    *((float4*)(out + ((size_t)pix << 6) + c4)) = r;
}

// ---------------------------------------------------------------------------
// Pass 2 (fused): NHWC -> NCHW. Block = 512 threads owns 128 pixels x 64 ch.
// Gather phase mirrors pass 1 (16 threads/pixel, 4 LDG.128) x4 iterations.
// Smem tile st[c][p] with XOR swizzle p^(2*chunk): conflict-free STS.32 and
// LDS.128. Write phase: warp = one channel, 512B contiguous STG per instr.
// ---------------------------------------------------------------------------
__global__ __launch_bounds__(512) void gather_nhwc_to_nchw_kernel(
    const float* __restrict__ feat,    // [N,H,W,C] intermediate
    const float2* __restrict__ grid,   // [N,H,W]
    float* __restrict__ out)           // [N,C,H,W]
{
    __shared__ float st[64 * 128];     // [channel][pixel], swizzled (32 KB)

    int pix0 = blockIdx.x * 128;       // 128 consecutive pixels, same batch
    int n   = pix0 >> 16;
    int hw0 = pix0 & (HW - 1);

    int t = threadIdx.x;
    const float* fb = feat + (size_t)n * PLANE;

    #pragma unroll
    for (int k = 0; k < 4; ++k) {
        int item  = k * 512 + t;
        int p     = item >> 4;         // local pixel 0..127
        int chunk = item & 15;         // channel chunk
        int c4    = chunk << 2;

        SampleW s = compute_weights(__ldg(&grid[pix0 + p]));
        float4 r = bilerp4(fb, s, c4);

        int pp = p ^ (chunk << 1);     // swizzled pixel index
        st[(c4 + 0) * 128 + pp] = r.x;
        st[(c4 + 1) * 128 + pp] = r.y;
        st[(c4 + 2) * 128 + pp] = r.z;
        st[(c4 + 3) * 128 + pp] = r.w;
    }
    __syncthreads();

    // Write phase: warp w handles channel c = k*16+w; lane l covers p=4l..4l+3.
    int w = t >> 5;
    int l = t & 31;
    float* ob = out + (size_t)n * PLANE + hw0 + 4 * l;

    #pragma unroll
    for (int k = 0; k < 4; ++k) {
        int c = k * 16 + w;
        int X = (c >> 2) << 1;                 // swizzle constant for this row
        int base = (4 * l) ^ (X & 28);         // aligned float4 base, bijection over lanes
        float4 v = *((const float4*)&st[c * 128 + base]);
        if (X & 2) {                           // undo low-bit swizzle: i -> i^2
            float tx = v.x; v.x = v.z; v.z = tx;
            float ty = v.y; v.y = v.w; v.w = ty;
        }
        *((float4*)(ob + (size_t)c * HW)) = v;
    }
}

extern "C" void kernel_launch(void* const* d_in, const int* in_sizes, int n_in,
                              void* d_out, int out_size)
{
    const float*  feat = (const float*)d_in[0];
    const float2* grid = (const float2*)d_in[1];
    float* out = (float*)d_out;

    float *a = nullptr, *b = nullptr;
    cudaGetSymbolAddress((void**)&a, g_a);
    cudaGetSymbolAddress((void**)&b, g_b);

    // 1. feature NCHW -> NHWC
    nchw_to_nhwc_kernel<<<dim3(HW / 32, 1, Nb), dim3(32, 8)>>>(feat, a);

    // 2. pass 1 gather (NHWC -> NHWC)
    gather_nhwc_kernel<<<(NPIX * 16) / 256, 256>>>(a, grid, b);

    // 3. pass 2 gather fused with output transpose (NHWC -> NCHW)
    gather_nhwc_to_nchw_kernel<<<NPIX / 128, 512>>>(b, grid, out);
}

// round 9
// speedup vs baseline: 7.4272x; 1.4249x over previous
#include <cuda_runtime.h>
#include <cuda_fp16.h>
#include <cstdint>

#define Nb 8
#define C  64
#define H  256
#define W  256
#define HW (H * W)             // 65536
#define NPIX (Nb * HW)         // 524288
#define PLANE ((size_t)C * HW) // elements per batch

// Two 64 MiB fp16 NHWC scratch buffers (static device memory, no alloc).
__device__ __half g_ah[(size_t)Nb * PLANE];
__device__ __half g_bh[(size_t)Nb * PLANE];

// ---------------------------------------------------------------------------
// NCHW f32 -> NHWC fp16 transpose. Block=(32,8); tile 64ch x 128hw.
// Loads: 8 x LDG.128 per thread (2 channel rows x 4 j-iters).
// Smem: half tile[128px][66ch]; write phase emits 128B/pixel contiguous.
// ---------------------------------------------------------------------------
__global__ __launch_bounds__(256) void nchw_to_nhwc_h_kernel(
    const float* __restrict__ in, __half* __restrict__ outh)
{
    __shared__ __half tile[128][66];   // [pixel][channel], row=132B (word aligned)
    size_t boff = (size_t)blockIdx.z * PLANE;
    int hw0 = blockIdx.x * 128;
    int tx = threadIdx.x, ty = threadIdx.y;

    // load: channel pair (ch, ch+1), 4 consecutive hw each, pack half2 per pixel
    #pragma unroll
    for (int j = 0; j < 4; ++j) {
        int ch = 2 * ty + 16 * j;
        float4 v0 = *((const float4*)(in + boff + (size_t)ch * HW + hw0 + 4 * tx));
        float4 v1 = *((const float4*)(in + boff + (size_t)(ch + 1) * HW + hw0 + 4 * tx));
        *((__half2*)&tile[4 * tx + 0][ch]) = __floats2half2_rn(v0.x, v1.x);
        *((__half2*)&tile[4 * tx + 1][ch]) = __floats2half2_rn(v0.y, v1.y);
        *((__half2*)&tile[4 * tx + 2][ch]) = __floats2half2_rn(v0.z, v1.z);
        *((__half2*)&tile[4 * tx + 3][ch]) = __floats2half2_rn(v0.w, v1.w);
    }
    __syncthreads();

    // write: warp = one pixel per iter; lane l stores word (ch 2l,2l+1); 128B/instr
    #pragma unroll
    for (int i = 0; i < 16; ++i) {
        int p = ty * 16 + i;
        uint32_t wv = ((const uint32_t*)&tile[p][0])[tx];   // word 33p+tx: conflict-free
        ((uint32_t*)(outh + boff + ((size_t)(hw0 + p) << 6)))[tx] = wv;
    }
}

// ---------------------------------------------------------------------------
// Shared coordinate/weight computation
// ---------------------------------------------------------------------------
struct SampleW {
    float w00, w01, w10, w11;
    int o00, o01, o10, o11;
};

__device__ __forceinline__ SampleW compute_weights(float2 g)
{
    float ix = ((g.x + 1.0f) * (float)W - 1.0f) * 0.5f;
    float iy = ((g.y + 1.0f) * (float)H - 1.0f) * 0.5f;

    float ix0f = floorf(ix);
    float iy0f = floorf(iy);
    float fx = ix - ix0f;
    float fy = iy - iy0f;

    int x0 = (int)ix0f, y0 = (int)iy0f;
    int x1 = x0 + 1,    y1 = y0 + 1;

    float vx0 = (x0 >= 0 && x0 < W) ? 1.0f : 0.0f;
    float vx1 = (x1 >= 0 && x1 < W) ? 1.0f : 0.0f;
    float vy0 = (y0 >= 0 && y0 < H) ? 1.0f : 0.0f;
    float vy1 = (y1 >= 0 && y1 < H) ? 1.0f : 0.0f;

    int cx0 = min(max(x0, 0), W - 1);
    int cx1 = min(max(x1, 0), W - 1);
    int cy0 = min(max(y0, 0), H - 1);
    int cy1 = min(max(y1, 0), H - 1);

    SampleW s;
    s.w00 = (1.0f - fx) * (1.0f - fy) * vx0 * vy0;
    s.w01 = fx * (1.0f - fy) * vx1 * vy0;
    s.w10 = (1.0f - fx) * fy * vx0 * vy1;
    s.w11 = fx * fy * vx1 * vy1;
    s.o00 = cy0 * W + cx0;
    s.o01 = cy0 * W + cx1;
    s.o10 = cy1 * W + cx0;
    s.o11 = cy1 * W + cx1;
    return s;
}

// 8-channel fp16 bilinear: 4 corner LDG.128 (uint4 = 8 halves), f32 math.
struct F8 { float v[8]; };

__device__ __forceinline__ F8 bilerp8h(const __half* fb, const SampleW& s, int c8)
{
    uint4 A = __ldg((const uint4*)(fb + ((size_t)s.o00 << 6) + c8));
    uint4 B = __ldg((const uint4*)(fb + ((size_t)s.o01 << 6) + c8));
    uint4 Cc = __ldg((const uint4*)(fb + ((size_t)s.o10 << 6) + c8));
    uint4 D = __ldg((const uint4*)(fb + ((size_t)s.o11 << 6) + c8));

    F8 r;
    const uint32_t* aw = (const uint32_t*)&A;
    const uint32_t* bw = (const uint32_t*)&B;
    const uint32_t* cw = (const uint32_t*)&Cc;
    const uint32_t* dw = (const uint32_t*)&D;
    #pragma unroll
    for (int i = 0; i < 4; ++i) {
        float2 af = __half22float2(*(const __half2*)&aw[i]);
        float2 bf = __half22float2(*(const __half2*)&bw[i]);
        float2 cf = __half22float2(*(const __half2*)&cw[i]);
        float2 df = __half22float2(*(const __half2*)&dw[i]);
        r.v[2 * i + 0] = af.x * s.w00 + bf.x * s.w01 + cf.x * s.w10 + df.x * s.w11;
        r.v[2 * i + 1] = af.y * s.w00 + bf.y * s.w01 + cf.y * s.w10 + df.y * s.w11;
    }
    return r;
}

// ---------------------------------------------------------------------------
// Pass 1: fp16 NHWC -> fp16 NHWC. 8 threads/pixel, 8 channels each.
// ---------------------------------------------------------------------------
__global__ __launch_bounds__(256) void gather_nhwc_h_kernel(
    const __half* __restrict__ feat,
    const float2* __restrict__ grid,
    __half* __restrict__ outh)
{
    int tid = blockIdx.x * blockDim.x + threadIdx.x;
    int pix = tid >> 3;
    int c8  = (tid & 7) << 3;
    if (pix >= NPIX) return;

    int n = pix >> 16;
    SampleW s = compute_weights(__ldg(&grid[pix]));
    F8 r = bilerp8h(feat + (size_t)n * PLANE, s, c8);

    uint4 o;
    uint32_t* ow = (uint32_t*)&o;
    #pragma unroll
    for (int i = 0; i < 4; ++i) {
        __half2 h = __floats2half2_rn(r.v[2 * i], r.v[2 * i + 1]);
        ow[i] = *(const uint32_t*)&h;
    }
    *((uint4*)(outh + ((size_t)pix << 6) + c8)) = o;
}

// ---------------------------------------------------------------------------
// Pass 2 (fused): fp16 NHWC -> f32 NCHW. Block = 512 threads, 128 pixels.
// Smem st[c][p^((c>>3)<<2)] f32: conflict-free STS.32 and aligned LDS.128,
// no component swap. Write phase: warp = one channel, 512B contiguous STG.
// ---------------------------------------------------------------------------
__global__ __launch_bounds__(512) void gather_h_to_nchw_kernel(
    const __half* __restrict__ feat,   // [N,H,W,C] fp16 intermediate
    const float2* __restrict__ grid,   // [N,H,W]
    float* __restrict__ out)           // [N,C,H,W] f32
{
    __shared__ float st[64 * 128];     // [channel][pixel], swizzled (32 KB)

    int pix0 = blockIdx.x * 128;
    int n   = pix0 >> 16;
    int hw0 = pix0 & (HW - 1);

    int t = threadIdx.x;
    const __half* fb = feat + (size_t)n * PLANE;

    #pragma unroll
    for (int k = 0; k < 2; ++k) {
        int item  = k * 512 + t;
        int p     = item >> 3;         // local pixel 0..127
        int chunk = item & 7;          // 8-channel chunk
        int c8    = chunk << 3;

        SampleW s = compute_weights(__ldg(&grid[pix0 + p]));
        F8 r = bilerp8h(fb, s, c8);

        int pp = p ^ (chunk << 2);     // swizzled pixel index (conflict-free)
        #pragma unroll
        for (int i = 0; i < 8; ++i)
            st[(c8 + i) * 128 + pp] = r.v[i];
    }
    __syncthreads();

    // Write: warp w -> channel c=k*16+w; lane l -> pixels 4l..4l+3 (swizzled read).
    int w = t >> 5;
    int l = t & 31;
    float* ob = out + (size_t)n * PLANE + hw0 + 4 * l;

    #pragma unroll
    for (int k = 0; k < 4; ++k) {
        int c = k * 16 + w;
        int X = (c >> 3) << 2;                 // 4-aligned swizzle constant
        int base = (4 * l) ^ X;                // aligned float4 base
        float4 v = *((const float4*)&st[c * 128 + base]);  // pixels 4l..4l+3 in order
        *((float4*)(ob + (size_t)c * HW)) = v;
    }
}

extern "C" void kernel_launch(void* const* d_in, const int* in_sizes, int n_in,
                              void* d_out, int out_size)
{
    const float*  feat = (const float*)d_in[0];
    const float2* grid = (const float2*)d_in[1];
    float* out = (float*)d_out;

    __half *a = nullptr, *b = nullptr;
    cudaGetSymbolAddress((void**)&a, g_ah);
    cudaGetSymbolAddress((void**)&b, g_bh);

    // 1. feature NCHW f32 -> NHWC fp16
    nchw_to_nhwc_h_kernel<<<dim3(HW / 128, 1, Nb), dim3(32, 8)>>>(feat, a);

    // 2. pass 1 gather (fp16 NHWC -> fp16 NHWC)
    gather_nhwc_h_kernel<<<(NPIX * 8) / 256, 256>>>(a, grid, b);

    // 3. pass 2 gather fused with output transpose (fp16 NHWC -> f32 NCHW)
    gather_h_to_nchw_kernel<<<NPIX / 128, 512>>>(b, grid, out);
}

// round 12
// speedup vs baseline: 7.7159x; 1.0389x over previous
#include <cuda_runtime.h>
#include <cuda_fp16.h>
#include <cstdint>

#define Nb 8
#define C  64
#define H  256
#define W  256
#define HW (H * W)             // 65536
#define NPIX (Nb * HW)         // 524288
#define PLANE ((size_t)C * HW) // elements per batch

// Two 64 MiB fp16 NHWC scratch buffers (static device memory, no alloc).
__device__ __half g_ah[(size_t)Nb * PLANE];
__device__ __half g_bh[(size_t)Nb * PLANE];

// ---------------------------------------------------------------------------
// NCHW f32 -> NHWC fp16 transpose. (unchanged, 30.3us)
// ---------------------------------------------------------------------------
__global__ __launch_bounds__(256) void nchw_to_nhwc_h_kernel(
    const float* __restrict__ in, __half* __restrict__ outh)
{
    __shared__ __half tile[128][66];
    size_t boff = (size_t)blockIdx.z * PLANE;
    int hw0 = blockIdx.x * 128;
    int tx = threadIdx.x, ty = threadIdx.y;

    #pragma unroll
    for (int j = 0; j < 4; ++j) {
        int ch = 2 * ty + 16 * j;
        float4 v0 = *((const float4*)(in + boff + (size_t)ch * HW + hw0 + 4 * tx));
        float4 v1 = *((const float4*)(in + boff + (size_t)(ch + 1) * HW + hw0 + 4 * tx));
        *((__half2*)&tile[4 * tx + 0][ch]) = __floats2half2_rn(v0.x, v1.x);
        *((__half2*)&tile[4 * tx + 1][ch]) = __floats2half2_rn(v0.y, v1.y);
        *((__half2*)&tile[4 * tx + 2][ch]) = __floats2half2_rn(v0.z, v1.z);
        *((__half2*)&tile[4 * tx + 3][ch]) = __floats2half2_rn(v0.w, v1.w);
    }
    __syncthreads();

    #pragma unroll
    for (int i = 0; i < 16; ++i) {
        int p = ty * 16 + i;
        uint32_t wv = ((const uint32_t*)&tile[p][0])[tx];
        ((uint32_t*)(outh + boff + ((size_t)(hw0 + p) << 6)))[tx] = wv;
    }
}

// ---------------------------------------------------------------------------
// Shared coordinate/weight computation
// ---------------------------------------------------------------------------
struct SampleW {
    float w00, w01, w10, w11;
    int o00, o01, o10, o11;
};

__device__ __forceinline__ SampleW compute_weights(float2 g)
{
    float ix = ((g.x + 1.0f) * (float)W - 1.0f) * 0.5f;
    float iy = ((g.y + 1.0f) * (float)H - 1.0f) * 0.5f;

    float ix0f = floorf(ix);
    float iy0f = floorf(iy);
    float fx = ix - ix0f;
    float fy = iy - iy0f;

    int x0 = (int)ix0f, y0 = (int)iy0f;
    int x1 = x0 + 1,    y1 = y0 + 1;

    float vx0 = (x0 >= 0 && x0 < W) ? 1.0f : 0.0f;
    float vx1 = (x1 >= 0 && x1 < W) ? 1.0f : 0.0f;
    float vy0 = (y0 >= 0 && y0 < H) ? 1.0f : 0.0f;
    float vy1 = (y1 >= 0 && y1 < H) ? 1.0f : 0.0f;

    int cx0 = min(max(x0, 0), W - 1);
    int cx1 = min(max(x1, 0), W - 1);
    int cy0 = min(max(y0, 0), H - 1);
    int cy1 = min(max(y1, 0), H - 1);

    SampleW s;
    s.w00 = (1.0f - fx) * (1.0f - fy) * vx0 * vy0;
    s.w01 = fx * (1.0f - fy) * vx1 * vy0;
    s.w10 = (1.0f - fx) * fy * vx0 * vy1;
    s.w11 = fx * fy * vx1 * vy1;
    s.o00 = cy0 * W + cx0;
    s.o01 = cy0 * W + cx1;
    s.o10 = cy1 * W + cx0;
    s.o11 = cy1 * W + cx1;
    return s;
}

struct F8 { float v[8]; };

__device__ __forceinline__ F8 combine8(uint4 A, uint4 B, uint4 Cc, uint4 D,
                                       const SampleW& s)
{
    F8 r;
    const uint32_t* aw = (const uint32_t*)&A;
    const uint32_t* bw = (const uint32_t*)&B;
    const uint32_t* cw = (const uint32_t*)&Cc;
    const uint32_t* dw = (const uint32_t*)&D;
    #pragma unroll
    for (int i = 0; i < 4; ++i) {
        float2 af = __half22float2(*(const __half2*)&aw[i]);
        float2 bf = __half22float2(*(const __half2*)&bw[i]);
        float2 cf = __half22float2(*(const __half2*)&cw[i]);
        float2 df = __half22float2(*(const __half2*)&dw[i]);
        r.v[2 * i + 0] = af.x * s.w00 + bf.x * s.w01 + cf.x * s.w10 + df.x * s.w11;
        r.v[2 * i + 1] = af.y * s.w00 + bf.y * s.w01 + cf.y * s.w10 + df.y * s.w11;
    }
    return r;
}

__device__ __forceinline__ uint4 pack8(const F8& r)
{
    uint4 o;
    uint32_t* ow = (uint32_t*)&o;
    #pragma unroll
    for (int i = 0; i < 4; ++i) {
        __half2 h = __floats2half2_rn(r.v[2 * i], r.v[2 * i + 1]);
        ow[i] = *(const uint32_t*)&h;
    }
    return o;
}

// ---------------------------------------------------------------------------
// Pass 1: fp16 NHWC -> fp16 NHWC. 8 threads/pixel, TWO pixels per thread
// (pix and pix + NPIX/2) -> 8 outstanding LDG.128 before any consumption.
// ---------------------------------------------------------------------------
__global__ __launch_bounds__(256) void gather_nhwc_h_kernel(
    const __half* __restrict__ feat,
    const float2* __restrict__ grid,
    __half* __restrict__ outh)
{
    int tid = blockIdx.x * blockDim.x + threadIdx.x;   // 0 .. NPIX*8/2 - 1
    int pixA = tid >> 3;
    int c8   = (tid & 7) << 3;
    int pixB = pixA + NPIX / 2;

    SampleW sA = compute_weights(__ldg(&grid[pixA]));
    SampleW sB = compute_weights(__ldg(&grid[pixB]));

    const __half* fA = feat + (size_t)(pixA >> 16) * PLANE;
    const __half* fB = feat + (size_t)(pixB >> 16) * PLANE;

    // issue all 8 gathers up front (MLP=8)
    uint4 A0 = __ldg((const uint4*)(fA + ((size_t)sA.o00 << 6) + c8));
    uint4 A1 = __ldg((const uint4*)(fA + ((size_t)sA.o01 << 6) + c8));
    uint4 A2 = __ldg((const uint4*)(fA + ((size_t)sA.o10 << 6) + c8));
    uint4 A3 = __ldg((const uint4*)(fA + ((size_t)sA.o11 << 6) + c8));
    uint4 B0 = __ldg((const uint4*)(fB + ((size_t)sB.o00 << 6) + c8));
    uint4 B1 = __ldg((const uint4*)(fB + ((size_t)sB.o01 << 6) + c8));
    uint4 B2 = __ldg((const uint4*)(fB + ((size_t)sB.o10 << 6) + c8));
    uint4 B3 = __ldg((const uint4*)(fB + ((size_t)sB.o11 << 6) + c8));

    F8 rA = combine8(A0, A1, A2, A3, sA);
    *((uint4*)(outh + ((size_t)pixA << 6) + c8)) = pack8(rA);
    F8 rB = combine8(B0, B1, B2, B3, sB);
    *((uint4*)(outh + ((size_t)pixB << 6) + c8)) = pack8(rB);
}

// ---------------------------------------------------------------------------
// Pass 2 (fused): fp16 NHWC -> f32 NCHW. Streaming stores on output.
// ---------------------------------------------------------------------------
__global__ __launch_bounds__(512) void gather_h_to_nchw_kernel(
    const __half* __restrict__ feat,   // [N,H,W,C] fp16 intermediate
    const float2* __restrict__ grid,   // [N,H,W]
    float* __restrict__ out)           // [N,C,H,W] f32
{
    __shared__ float st[64 * 128];     // [channel][pixel], swizzled (32 KB)

    int pix0 = blockIdx.x * 128;
    int n   = pix0 >> 16;
    int hw0 = pix0 & (HW - 1);

    int t = threadIdx.x;
    const __half* fb = feat + (size_t)n * PLANE;

    #pragma unroll
    for (int k = 0; k < 2; ++k) {
        int item  = k * 512 + t;
        int p     = item >> 3;
        int chunk = item & 7;
        int c8    = chunk << 3;

        SampleW s = compute_weights(__ldg(&grid[pix0 + p]));
        uint4 A = __ldg((const uint4*)(fb + ((size_t)s.o00 << 6) + c8));
        uint4 B = __ldg((const uint4*)(fb + ((size_t)s.o01 << 6) + c8));
        uint4 Cc = __ldg((const uint4*)(fb + ((size_t)s.o10 << 6) + c8));
        uint4 D = __ldg((const uint4*)(fb + ((size_t)s.o11 << 6) + c8));
        F8 r = combine8(A, B, Cc, D, s);

        int pp = p ^ (chunk << 2);     // swizzled pixel index (conflict-free)
        #pragma unroll
        for (int i = 0; i < 8; ++i)
            st[(c8 + i) * 128 + pp] = r.v[i];
    }
    __syncthreads();

    // Write: warp w -> channel c=k*16+w; lane l -> pixels 4l..4l+3.
    int w = t >> 5;
    int l = t & 31;
    float* ob = out + (size_t)n * PLANE + hw0 + 4 * l;

    #pragma unroll
    for (int k = 0; k < 4; ++k) {
        int c = k * 16 + w;
        int X = (c >> 3) << 2;
        int base = (4 * l) ^ X;
        float4 v = *((const float4*)&st[c * 128 + base]);
        __stcs((float4*)(ob + (size_t)c * HW), v);   // evict-streaming: don't pollute L2
    }
}

extern "C" void kernel_launch(void* const* d_in, const int* in_sizes, int n_in,
                              void* d_out, int out_size)
{
    const float*  feat = (const float*)d_in[0];
    const float2* grid = (const float2*)d_in[1];
    float* out = (float*)d_out;

    __half *a = nullptr, *b = nullptr;
    cudaGetSymbolAddress((void**)&a, g_ah);
    cudaGetSymbolAddress((void**)&b, g_bh);

    // 1. feature NCHW f32 -> NHWC fp16
    nchw_to_nhwc_h_kernel<<<dim3(HW / 128, 1, Nb), dim3(32, 8)>>>(feat, a);

    // 2. pass 1 gather (fp16 NHWC -> fp16 NHWC), 2 pixels per thread
    gather_nhwc_h_kernel<<<(NPIX * 8 / 2) / 256, 256>>>(a, grid, b);

    // 3. pass 2 gather fused with output transpose (fp16 NHWC -> f32 NCHW)
    gather_h_to_nchw_kernel<<<NPIX / 128, 512>>>(b, grid, out);
}